// round 4
// baseline (speedup 1.0000x reference)
#include <cuda_runtime.h>

#define N_ROWS   100000
#define NBINS    512
#define BATCH    8192
#define KNN      16
#define COL_BLKS 64
#define ROWS_PER_COLBLK 128
#define THREADS  512
#define TOTAL_BLKS (BATCH + COL_BLKS)

// Scratch (device allocs forbidden). Fully rewritten every launch.
__device__ float        g_wpart[BATCH];             // w[i] * sum_j add[i][j]
__device__ float        g_bpart[COL_BLKS * NBINS];  // per-strip column sums
__device__ unsigned int g_count = 0;                // ticket; reset by finalizer

__global__ __launch_bounds__(THREADS) void fused_kernel(
    const float* __restrict__ outputs,
    const float* __restrict__ y,
    const float* __restrict__ weights,
    float* __restrict__ d_out)
{
    __shared__ float    s_base[NBINS];
    __shared__ float    s_add[KNN];
    __shared__ unsigned s_ticket;
    __shared__ float    s_max[THREADS];
    __shared__ float    s_min[THREADS];
    __shared__ double   s_sum[THREADS];

    const int bid = blockIdx.x;
    const int tid = threadIdx.x;

    if (bid < COL_BLKS) {
        // ---- Column-sum strip (front of grid -> overlaps the pair wave).
        // 512 threads, thread t owns bin t; 128 rows, coalesced.
        const float* p = outputs + (size_t)bid * ROWS_PER_COLBLK * NBINS + tid;
        float s = 0.f;
#pragma unroll 8
        for (int r = 0; r < ROWS_PER_COLBLK; r++) s += p[(size_t)r * NBINS];
        g_bpart[bid * NBINS + tid] = s;
    } else {
        // ---- Pair work for batch row i: 16 warps, warp j owns neighbor j.
        const int i    = bid - COL_BLKS;
        const int warp = tid >> 5;
        const int lane = tid & 31;

        // Stage base row in SMEM (128 x float4).
        const float4* base4 = reinterpret_cast<const float4*>(outputs + (size_t)i * NBINS);
        float4* s4 = reinterpret_cast<float4*>(s_base);
        if (tid < NBINS / 4) s4[tid] = base4[tid];

        // Gather neighbor row: 4 independent LDG.128 per lane, issued before the barrier.
        const int nn = (int)y[i * KNN + warp];
        const float4* nbr4 = reinterpret_cast<const float4*>(outputs + (size_t)nn * NBINS);
        float4 n0 = nbr4[lane];
        float4 n1 = nbr4[32 + lane];
        float4 n2 = nbr4[64 + lane];
        float4 n3 = nbr4[96 + lane];

        __syncthreads();   // s_base ready

        float4 b0 = s4[lane], b1 = s4[32 + lane], b2 = s4[64 + lane], b3 = s4[96 + lane];

        float m0 = fmaxf(fmaxf(b0.x + n0.x, b0.y + n0.y), fmaxf(b0.z + n0.z, b0.w + n0.w));
        float m1 = fmaxf(fmaxf(b1.x + n1.x, b1.y + n1.y), fmaxf(b1.z + n1.z, b1.w + n1.w));
        float m2 = fmaxf(fmaxf(b2.x + n2.x, b2.y + n2.y), fmaxf(b2.z + n2.z, b2.w + n2.w));
        float m3 = fmaxf(fmaxf(b3.x + n3.x, b3.y + n3.y), fmaxf(b3.z + n3.z, b3.w + n3.w));
        float m  = fmaxf(fmaxf(m0, m1), fmaxf(m2, m3));

#pragma unroll
        for (int o = 16; o; o >>= 1)
            m = fmaxf(m, __shfl_xor_sync(0xffffffffu, m, o));
        if (lane == 0) s_add[warp] = m;
        __syncthreads();

        if (tid == 0) {
            float s = 0.f;
#pragma unroll
            for (int j = 0; j < KNN; j++) s += s_add[j];
            d_out[3 + i] = fmaxf((2.0f - s * (1.0f / KNN)) * 0.5f, 0.5f);  // booster
            g_wpart[i]   = s * weights[i];
        }
    }

    // ---- Ticket with RELEASE atomic: orders our scratch stores for the
    // finalizer WITHOUT a gpu-scope fence (no CCTL.IVALL / L1D flush).
    if (tid == 0) {
        unsigned t;
        asm volatile("atom.add.release.gpu.global.u32 %0, [%1], 1;"
                     : "=r"(t) : "l"(&g_count) : "memory");
        s_ticket = t;
    }
    __syncthreads();

    if (s_ticket == TOTAL_BLKS - 1) {
        // Acquire side — single CTA, cost irrelevant.
        asm volatile("fence.acq_rel.gpu;" ::: "memory");

        // Column totals: thread t owns bin t.
        float col = 0.f;
#pragma unroll 8
        for (int b = 0; b < COL_BLKS; b++) col += __ldcg(&g_bpart[b * NBINS + tid]);

        // Weighted-sum reduction (double accumulation, fixed order).
        double ws = 0.0;
#pragma unroll 4
        for (int r = tid; r < BATCH; r += THREADS) ws += (double)__ldcg(&g_wpart[r]);

        s_max[tid] = col; s_min[tid] = col; s_sum[tid] = ws;
        __syncthreads();
        for (int o = THREADS / 2; o; o >>= 1) {
            if (tid < o) {
                s_max[tid] = fmaxf(s_max[tid], s_max[tid + o]);
                s_min[tid] = fminf(s_min[tid], s_min[tid + o]);
                s_sum[tid] += s_sum[tid + o];
            }
            __syncthreads();
        }

        if (tid == 0) {
            float bspread  = s_max[0] - s_min[0];
            float ratio    = bspread / ((float)N_ROWS / (float)NBINS);
            float add_mean = (float)(s_sum[0] / (double)(BATCH * KNN));
            float d        = 2.0f - add_mean;
            d = d * d;
            d_out[0] = ratio + d;   // cost
            d_out[1] = d;           // diff
            d_out[2] = ratio;       // b / target_b
            g_count  = 0;           // reset for next graph replay
        }
    }
}

extern "C" void kernel_launch(void* const* d_in, const int* in_sizes, int n_in,
                              void* d_out, int out_size)
{
    const float* outputs = (const float*)d_in[0];  // (100000, 512) f32
    const float* y       = (const float*)d_in[1];  // (8192, 16)   f32 indices
    const float* weights = (const float*)d_in[2];  // (8192,)      f32
    float* out = (float*)d_out;                    // [cost, diff, ratio, boost(8192)]

    fused_kernel<<<TOTAL_BLKS, THREADS>>>(outputs, y, weights, out);
}

// round 5
// speedup vs baseline: 1.0459x; 1.0459x over previous
#include <cuda_runtime.h>

#define N_ROWS   100000
#define NBINS    512
#define BATCH    8192
#define KNN      16
#define CS_BLKS  128
#define CS_ROWS  (BATCH / CS_BLKS)      // 64 rows per colsum CTA
#define THREADS  512

// Scratch (device allocs forbidden). Fully rewritten every launch.
__device__ float        g_wpart[BATCH];            // w[i] * sum_j add[i][j]
__device__ float        g_bpart[CS_BLKS * NBINS];  // per-strip column sums
__device__ unsigned int g_count = 0;               // ticket; reset by finalizer

// ---------------------------------------------------------------------------
// Kernel A: one CTA per batch row i. 16 warps, warp j owns neighbor j.
// No smem staging: base row read from global per-warp (L1 hit for 15/16 warps),
// so there is NO barrier before the loads — warps run fully independently.
// ---------------------------------------------------------------------------
__global__ __launch_bounds__(THREADS) void pair_kernel(
    const float* __restrict__ outputs,
    const float* __restrict__ y,
    const float* __restrict__ weights,
    float* __restrict__ out_boost)   // -> d_out + 3
{
    __shared__ float s_add[KNN];

    const int i    = blockIdx.x;
    const int tid  = threadIdx.x;
    const int warp = tid >> 5;
    const int lane = tid & 31;

    const int nn = (int)y[i * KNN + warp];
    const float4* nbr4  = reinterpret_cast<const float4*>(outputs + (size_t)nn * NBINS);
    const float4* base4 = reinterpret_cast<const float4*>(outputs + (size_t)i  * NBINS);

    // 8 independent loads per lane: 4 DRAM-ish gathers + 4 L1-shared base loads.
    float4 n0 = nbr4[lane];
    float4 n1 = nbr4[32 + lane];
    float4 n2 = nbr4[64 + lane];
    float4 n3 = nbr4[96 + lane];
    float4 b0 = base4[lane];
    float4 b1 = base4[32 + lane];
    float4 b2 = base4[64 + lane];
    float4 b3 = base4[96 + lane];

    float m0 = fmaxf(fmaxf(b0.x + n0.x, b0.y + n0.y), fmaxf(b0.z + n0.z, b0.w + n0.w));
    float m1 = fmaxf(fmaxf(b1.x + n1.x, b1.y + n1.y), fmaxf(b1.z + n1.z, b1.w + n1.w));
    float m2 = fmaxf(fmaxf(b2.x + n2.x, b2.y + n2.y), fmaxf(b2.z + n2.z, b2.w + n2.w));
    float m3 = fmaxf(fmaxf(b3.x + n3.x, b3.y + n3.y), fmaxf(b3.z + n3.z, b3.w + n3.w));
    float m  = fmaxf(fmaxf(m0, m1), fmaxf(m2, m3));

#pragma unroll
    for (int o = 16; o; o >>= 1)
        m = fmaxf(m, __shfl_xor_sync(0xffffffffu, m, o));
    if (lane == 0) s_add[warp] = m;
    __syncthreads();

    if (tid == 0) {
        float s = 0.f;
#pragma unroll
        for (int j = 0; j < KNN; j++) s += s_add[j];
        out_boost[i] = fmaxf((2.0f - s * (1.0f / KNN)) * 0.5f, 0.5f);  // booster
        g_wpart[i]   = s * weights[i];
    }
}

// ---------------------------------------------------------------------------
// Kernel B: column-sum strips + in-kernel finalizer via 128-CTA ticket.
// g_wpart is produced by kernel A (prior launch -> globally visible).
// ---------------------------------------------------------------------------
__global__ __launch_bounds__(THREADS) void epilogue_kernel(
    const float* __restrict__ outputs,
    float* __restrict__ d_out)
{
    __shared__ unsigned s_ticket;
    __shared__ float    s_max[THREADS];
    __shared__ float    s_min[THREADS];
    __shared__ double   s_sum[THREADS];

    const int bid = blockIdx.x;
    const int tid = threadIdx.x;

    // Strip sum: thread t owns bin t over CS_ROWS rows (coalesced).
    {
        const float* p = outputs + (size_t)bid * CS_ROWS * NBINS + tid;
        float s = 0.f;
#pragma unroll 8
        for (int r = 0; r < CS_ROWS; r++) s += p[(size_t)r * NBINS];
        g_bpart[bid * NBINS + tid] = s;
    }

    // Release ticket (128 atomics total — negligible).
    if (tid == 0) {
        unsigned t;
        asm volatile("atom.add.release.gpu.global.u32 %0, [%1], 1;"
                     : "=r"(t) : "l"(&g_count) : "memory");
        s_ticket = t;
    }
    __syncthreads();

    if (s_ticket == CS_BLKS - 1) {
        asm volatile("fence.acq_rel.gpu;" ::: "memory");   // acquire side

        // Column totals: thread t owns bin t.
        float col = 0.f;
#pragma unroll 8
        for (int b = 0; b < CS_BLKS; b++) col += __ldcg(&g_bpart[b * NBINS + tid]);

        // Weighted-sum (double accumulation, fixed order).
        double ws = 0.0;
#pragma unroll 4
        for (int r = tid; r < BATCH; r += THREADS) ws += (double)g_wpart[r];

        s_max[tid] = col; s_min[tid] = col; s_sum[tid] = ws;
        __syncthreads();
        for (int o = THREADS / 2; o; o >>= 1) {
            if (tid < o) {
                s_max[tid] = fmaxf(s_max[tid], s_max[tid + o]);
                s_min[tid] = fminf(s_min[tid], s_min[tid + o]);
                s_sum[tid] += s_sum[tid + o];
            }
            __syncthreads();
        }

        if (tid == 0) {
            float bspread  = s_max[0] - s_min[0];
            float ratio    = bspread / ((float)N_ROWS / (float)NBINS);
            float add_mean = (float)(s_sum[0] / (double)(BATCH * KNN));
            float d        = 2.0f - add_mean;
            d = d * d;
            d_out[0] = ratio + d;   // cost
            d_out[1] = d;           // diff
            d_out[2] = ratio;       // b / target_b
            g_count  = 0;           // reset for next graph replay
        }
    }
}

// ---------------------------------------------------------------------------
extern "C" void kernel_launch(void* const* d_in, const int* in_sizes, int n_in,
                              void* d_out, int out_size)
{
    const float* outputs = (const float*)d_in[0];  // (100000, 512) f32
    const float* y       = (const float*)d_in[1];  // (8192, 16)   f32 indices
    const float* weights = (const float*)d_in[2];  // (8192,)      f32
    float* out = (float*)d_out;                    // [cost, diff, ratio, boost(8192)]

    pair_kernel<<<BATCH, THREADS>>>(outputs, y, weights, out + 3);
    epilogue_kernel<<<CS_BLKS, THREADS>>>(outputs, out);
}